// round 10
// baseline (speedup 1.0000x reference)
#include <cuda_runtime.h>
#include <cstdint>

// -------------------- problem constants --------------------
#define TT   4
#define HH   128
#define WW   128
#define CC   256
#define HDN  8
#define KNBR 9
#define FF   32
#define MDIM (TT*HH*WW)   // 65536

// scratch (device globals; no runtime allocation allowed)
__device__ float g_v[(size_t)MDIM * CC];     // v = x @ v_w.T (fp32)
__device__ float g_agg[(size_t)MDIM * CC];   // aggregated (tf32-rounded bits)
__device__ float g_wv[(size_t)CC * CC];      // v_w tf32-rounded
__device__ float g_wp[(size_t)CC * CC];      // proj_w tf32-rounded

// -------------------- helpers --------------------
__device__ __forceinline__ uint32_t smem_u32(const void* p) {
    uint32_t a;
    asm("{ .reg .u64 t; cvta.to.shared.u64 t, %1; cvt.u32.u64 %0, t; }" : "=r"(a) : "l"(p));
    return a;
}
__device__ __forceinline__ uint32_t f2tf32(float x) {
    uint32_t r; asm("cvt.rna.tf32.f32 %0, %1;" : "=r"(r) : "f"(x)); return r;
}
__device__ __forceinline__ uint32_t rnd_u(uint32_t u) {
    uint32_t r; asm("cvt.rna.tf32.f32 %0, %1;" : "=r"(r) : "f"(__uint_as_float(u))); return r;
}
// Swizzle<3,4,3>
__device__ __forceinline__ uint32_t swz(uint32_t off) {
    return off ^ ((off >> 3) & 0x70);
}
__device__ __forceinline__ void cp_async16(uint32_t dst, const void* src) {
    asm volatile("cp.async.cg.shared.global [%0], [%1], 16;" :: "r"(dst), "l"(src));
}
__device__ __forceinline__ void cp_commit() {
    asm volatile("cp.async.commit_group;" ::: "memory");
}
template <int N>
__device__ __forceinline__ void cp_wait() {
    asm volatile("cp.async.wait_group %0;" :: "n"(N) : "memory");
}
__device__ __forceinline__ void ldmatrix_x4(uint32_t& r0, uint32_t& r1, uint32_t& r2, uint32_t& r3,
                                            uint32_t addr) {
    asm volatile("ldmatrix.sync.aligned.m8n8.x4.shared.b16 {%0,%1,%2,%3}, [%4];"
                 : "=r"(r0), "=r"(r1), "=r"(r2), "=r"(r3) : "r"(addr));
}
__device__ __forceinline__ void mma_tf32(float& c0, float& c1, float& c2, float& c3,
                                         uint32_t a0, uint32_t a1, uint32_t a2, uint32_t a3,
                                         uint32_t b0, uint32_t b1) {
    asm volatile("mma.sync.aligned.m16n8k8.row.col.f32.tf32.tf32.f32 "
                 "{%0,%1,%2,%3}, {%4,%5,%6,%7}, {%8,%9}, {%0,%1,%2,%3};"
                 : "+f"(c0), "+f"(c1), "+f"(c2), "+f"(c3)
                 : "r"(a0), "r"(a1), "r"(a2), "r"(a3), "r"(b0), "r"(b1));
}

// -------------------- tf32 pre-conversion (weights only; tiny) --------------------
__global__ __launch_bounds__(256)
void cvt_tf32_kernel(const float* __restrict__ in, float* __restrict__ out, int n4) {
    int i = blockIdx.x * blockDim.x + threadIdx.x;
    if (i < n4) {
        float4 v = ((const float4*)in)[i];
        uint4 o;
        o.x = f2tf32(v.x); o.y = f2tf32(v.y);
        o.z = f2tf32(v.z); o.w = f2tf32(v.w);
        ((uint4*)out)[i] = o;
    }
}

// -------------------- tf32 mma.sync GEMM (cp.async, 3-stage, BN=256) --------------------
// C[m,n] = sum_k A[m,k]*B[n,k] (+bias[n]); M=65536, N=256, K=256.
// CTA tile 128x256 (full N), 512 threads = 16 warps in 2(m) x 8(n), warp tile
// 64x32 (same as before). Each operand tile is read from DRAM exactly once.
#define GEMM_BM 128
#define GEMM_BN 256
#define GEMM_BK 32
#define A_TILE_BYTES (128 * 32 * 4)        // 16 KB
#define B_TILE_BYTES (256 * 32 * 4)        // 32 KB
#define BUF_BYTES  (A_TILE_BYTES + B_TILE_BYTES)   // 48 KB per stage
#define NSTAGE 3
#define DSMEM_BYTES (NSTAGE * BUF_BYTES)   // 144 KB
#define NKT (CC / GEMM_BK)                 // 8

template <bool CVT_A, bool CVT_B>
__global__ __launch_bounds__(512, 1)
void gemm_tf32_mma_kernel(const float* __restrict__ A,
                          const float* __restrict__ Bw,
                          const float* __restrict__ bias,
                          float* __restrict__ C)
{
    extern __shared__ char sm[];
    const int tid = threadIdx.x;
    const int wid = tid >> 5;          // 0..15
    const int lane = tid & 31;
    const int warp_m = wid >> 3;       // 0..1
    const int warp_n = wid & 7;        // 0..7
    const int bm = blockIdx.x * GEMM_BM;

    const uint32_t smbase = smem_u32(sm);

    // staging: st_c4 = float4 col (8 per 32-float row), st_row0 = 0..63
    const int st_c4  = tid & 7;
    const int st_row0 = tid >> 3;
    uint32_t a_off[2], b_off[4];
    #pragma unroll
    for (int i = 0; i < 2; i++)
        a_off[i] = swz((uint32_t)(st_row0 + 64 * i) * 128 + st_c4 * 16);
    #pragma unroll
    for (int j = 0; j < 4; j++)
        b_off[j] = swz((uint32_t)(st_row0 + 64 * j) * 128 + st_c4 * 16);

    const float* Abase = A + (size_t)(bm + st_row0) * CC + st_c4 * 4;
    const float* Bbase = Bw + (size_t)st_row0 * CC + st_c4 * 4;

    #pragma unroll
    for (int s = 0; s < 2; s++) {
        const uint32_t buf = smbase + s * BUF_BYTES;
        #pragma unroll
        for (int i = 0; i < 2; i++)
            cp_async16(buf + a_off[i], Abase + (size_t)i * 64 * CC + s * GEMM_BK);
        #pragma unroll
        for (int j = 0; j < 4; j++)
            cp_async16(buf + A_TILE_BYTES + b_off[j], Bbase + (size_t)j * 64 * CC + s * GEMM_BK);
        cp_commit();
    }

    float acc[4][4][4];
    #pragma unroll
    for (int mt = 0; mt < 4; mt++)
        #pragma unroll
        for (int nt = 0; nt < 4; nt++)
            #pragma unroll
            for (int r = 0; r < 4; r++)
                acc[mt][nt][r] = 0.0f;

    const int a_row_in = (lane & 7) + ((lane >> 3) & 1) * 8;
    const int a_chunk_hi = (lane >> 4);
    const int b_nt_off = (lane >> 4) * 8;
    const int b_row_in = (lane & 7);
    const int b_chunk_hi = (lane >> 3) & 1;

    #pragma unroll
    for (int kt = 0; kt < NKT; kt++) {
        if (kt + 1 < NKT) cp_wait<1>(); else cp_wait<0>();
        __syncthreads();
        if (kt + 2 < NKT) {
            const uint32_t buf = smbase + ((kt + 2) % NSTAGE) * BUF_BYTES;
            #pragma unroll
            for (int i = 0; i < 2; i++)
                cp_async16(buf + a_off[i], Abase + (size_t)i * 64 * CC + (kt + 2) * GEMM_BK);
            #pragma unroll
            for (int j = 0; j < 4; j++)
                cp_async16(buf + A_TILE_BYTES + b_off[j], Bbase + (size_t)j * 64 * CC + (kt + 2) * GEMM_BK);
            cp_commit();
        }

        const uint32_t abuf = smbase + (kt % NSTAGE) * BUF_BYTES;
        const uint32_t bbuf = abuf + A_TILE_BYTES;

        #pragma unroll
        for (int kk = 0; kk < 4; kk++) {
            uint32_t af[4][4];
            #pragma unroll
            for (int mt = 0; mt < 4; mt++) {
                const int row = warp_m * 64 + mt * 16 + a_row_in;
                const uint32_t off = swz((uint32_t)row * 128 + (kk * 2 + a_chunk_hi) * 16);
                ldmatrix_x4(af[mt][0], af[mt][1], af[mt][2], af[mt][3], abuf + off);
                if (CVT_A) {
                    af[mt][0] = rnd_u(af[mt][0]); af[mt][1] = rnd_u(af[mt][1]);
                    af[mt][2] = rnd_u(af[mt][2]); af[mt][3] = rnd_u(af[mt][3]);
                }
            }
            uint32_t bf[4][2];
            #pragma unroll
            for (int pair = 0; pair < 2; pair++) {
                const int row = warp_n * 32 + pair * 16 + b_nt_off + b_row_in;
                const uint32_t off = swz((uint32_t)row * 128 + (kk * 2 + b_chunk_hi) * 16);
                uint32_t r0, r1, r2, r3;
                ldmatrix_x4(r0, r1, r2, r3, bbuf + off);
                if (CVT_B) {
                    r0 = rnd_u(r0); r1 = rnd_u(r1); r2 = rnd_u(r2); r3 = rnd_u(r3);
                }
                bf[pair * 2 + 0][0] = r0; bf[pair * 2 + 0][1] = r1;
                bf[pair * 2 + 1][0] = r2; bf[pair * 2 + 1][1] = r3;
            }
            #pragma unroll
            for (int mt = 0; mt < 4; mt++)
                #pragma unroll
                for (int nt = 0; nt < 4; nt++)
                    mma_tf32(acc[mt][nt][0], acc[mt][nt][1], acc[mt][nt][2], acc[mt][nt][3],
                             af[mt][0], af[mt][1], af[mt][2], af[mt][3],
                             bf[nt][0], bf[nt][1]);
        }
    }

    // epilogue
    const int er = warp_m * 64 + (lane >> 2);
    const int ec = warp_n * 32 + (lane & 3) * 2;
    #pragma unroll
    for (int mt = 0; mt < 4; mt++) {
        #pragma unroll
        for (int nt = 0; nt < 4; nt++) {
            const int row = bm + er + mt * 16;
            const int col = ec + nt * 8;
            float2 lo = make_float2(acc[mt][nt][0], acc[mt][nt][1]);
            float2 hi = make_float2(acc[mt][nt][2], acc[mt][nt][3]);
            if (bias) {
                const float b0 = bias[col], b1 = bias[col + 1];
                lo.x += b0; lo.y += b1; hi.x += b0; hi.y += b1;
            }
            *(float2*)(C + (size_t)row * CC + col)       = lo;
            *(float2*)(C + (size_t)(row + 8) * CC + col) = hi;
        }
    }
}

// -------------------- flow-guided gather + aggregation (v4) --------------------
// Block = (hd, t, 16x16 h/w tile), 256 threads. Flows stored in smem as int8
// (values in [-3,3]) -> smem ~25 KB -> ~8 CTAs/SM. Stage-2 index math hoisted.
__global__ __launch_bounds__(256)
void gather_agg_kernel(const float* __restrict__ v,
                       const float* __restrict__ attn,
                       const int*   __restrict__ flows,
                       float* __restrict__ agg)
{
    __shared__ float s_attn[256 * KNBR];            // 9 KB
    __shared__ signed char s_fl[256 * KNBR * 3];    // ~6.8 KB
    __shared__ int   s_voff[256 * KNBR];            // 9 KB

    int b = blockIdx.x;
    const int w0 = (b & 7) << 4; b >>= 3;
    const int h0 = (b & 7) << 4; b >>= 3;
    const int t  = b & 3;
    const int hd = b >> 2;

    const int tid = threadIdx.x;

    // ---- stage 0: coalesced staging (16 row-segments) ----
    const size_t pos00 = ((size_t)((hd * TT + t) * HH + h0)) * WW + w0;
    {
        const float* ab = attn + pos00 * KNBR;
        #pragma unroll
        for (int j = tid; j < 16 * 144; j += 256) {      // 9 iters
            const int r = j / 144;
            const int c = j - r * 144;
            s_attn[r * 144 + c] = __ldg(ab + (size_t)r * (WW * KNBR) + c);
        }
        const int* fb = flows + pos00 * (KNBR * 3);
        #pragma unroll
        for (int j = tid; j < 16 * 432; j += 256) {      // 27 iters
            const int r = j / 432;
            const int c = j - r * 432;
            s_fl[r * 432 + c] = (signed char)__ldg(fb + (size_t)r * (WW * KNBR * 3) + c);
        }
    }
    __syncthreads();

    // ---- stage 1: clipped v-row offsets ----
    {
        const int pl = tid;
        const int w = w0 + (pl & 15);
        const int h = h0 + (pl >> 4);
        #pragma unroll
        for (int k = 0; k < KNBR; k++) {
            const int dt = s_fl[pl * 27 + k * 3 + 0];
            const int dh = s_fl[pl * 27 + k * 3 + 1];
            const int dw = s_fl[pl * 27 + k * 3 + 2];
            const int tt = min(max(t + dt, 0), TT - 1);
            const int hh = min(max(h + dh, 0), HH - 1);
            const int ww = min(max(w + dw, 0), WW - 1);
            s_voff[pl * KNBR + k] = ((tt * HH + hh) * WW + ww) * CC;
        }
    }
    __syncthreads();

    // ---- stage 2: gather + weighted sum (hoisted indexing) ----
    const int fq  = tid & 7;                 // invariant across i
    const int pl0 = tid >> 3;                // pl = pl0 + 32*i
    const int wfix = w0 + (pl0 & 15);        // invariant across i
    const int fbyte = hd * FF + fq * 4;
    const float* vb = v + fbyte;
    float* op = agg + ((size_t)((t * HH + (h0 + (pl0 >> 4))) * WW + wfix)) * CC + fbyte;
    int sb = pl0 * KNBR;

    #pragma unroll
    for (int i = 0; i < 8; i++) {
        float4 acc = make_float4(0.f, 0.f, 0.f, 0.f);
        #pragma unroll
        for (int k = 0; k < KNBR; k++) {
            const float wk = s_attn[sb + k];
            const int voff = s_voff[sb + k];
            const float4 vv = *(const float4*)(vb + voff);
            acc.x += wk * vv.x; acc.y += wk * vv.y;
            acc.z += wk * vv.z; acc.w += wk * vv.w;
        }
        uint4 o;
        o.x = f2tf32(acc.x); o.y = f2tf32(acc.y);
        o.z = f2tf32(acc.z); o.w = f2tf32(acc.w);
        *(uint4*)op = o;
        sb += 32 * KNBR;                 // next 32 positions
        op += (size_t)2 * WW * CC;       // +2 h-rows
    }
}

// -------------------- launch --------------------
extern "C" void kernel_launch(void* const* d_in, const int* in_sizes, int n_in,
                              void* d_out, int out_size)
{
    const float* x      = (const float*)d_in[0];
    const float* attn   = (const float*)d_in[1];
    const int*   flows  = (const int*)  d_in[2];
    const float* v_w    = (const float*)d_in[3];
    const float* proj_w = (const float*)d_in[4];
    const float* proj_b = (const float*)d_in[5];
    float* out = (float*)d_out;

    float *v_buf, *agg_buf, *wv, *wp;
    cudaGetSymbolAddress((void**)&v_buf,   g_v);
    cudaGetSymbolAddress((void**)&agg_buf, g_agg);
    cudaGetSymbolAddress((void**)&wv,      g_wv);
    cudaGetSymbolAddress((void**)&wp,      g_wp);

    cudaFuncSetAttribute(gemm_tf32_mma_kernel<true, false>,
                         cudaFuncAttributeMaxDynamicSharedMemorySize, DSMEM_BYTES);
    cudaFuncSetAttribute(gemm_tf32_mma_kernel<false, false>,
                         cudaFuncAttributeMaxDynamicSharedMemorySize, DSMEM_BYTES);

    // 0) pre-round weights (tiny: 2 x 256KB)
    {
        const int n4w = CC * CC / 4;   // 16384
        cvt_tf32_kernel<<<n4w / 256, 256>>>(v_w, wv, n4w);
        cvt_tf32_kernel<<<n4w / 256, 256>>>(proj_w, wp, n4w);
    }

    // 1) v = x @ v_w.T   (A rounded in-register once; B pre-rounded)
    gemm_tf32_mma_kernel<true, false><<<MDIM / GEMM_BM, 512, DSMEM_BYTES>>>(x, wv, nullptr, v_buf);

    // 2) gather + weighted aggregation
    {
        const int blocks = HDN * TT * 8 * 8;     // 2048
        gather_agg_kernel<<<blocks, 256>>>(v_buf, attn, flows, agg_buf);
    }

    // 3) out = agg @ proj_w.T + proj_b  (both operands pre-rounded)
    gemm_tf32_mma_kernel<false, false><<<MDIM / GEMM_BM, 512, DSMEM_BYTES>>>(agg_buf, wp, proj_b, out);
}

// round 12
// speedup vs baseline: 1.1772x; 1.1772x over previous
#include <cuda_runtime.h>
#include <cstdint>

// -------------------- problem constants --------------------
#define TT   4
#define HH   128
#define WW   128
#define CC   256
#define HDN  8
#define KNBR 9
#define FF   32
#define MDIM (TT*HH*WW)   // 65536

// scratch (device globals; no runtime allocation allowed)
__device__ float g_v[(size_t)MDIM * CC];     // v = x @ v_w.T (fp32)
__device__ float g_agg[(size_t)MDIM * CC];   // aggregated (tf32-rounded bits)
__device__ float g_wv[(size_t)CC * CC];      // v_w tf32-rounded
__device__ float g_wp[(size_t)CC * CC];      // proj_w tf32-rounded

// -------------------- helpers --------------------
__device__ __forceinline__ uint32_t smem_u32(const void* p) {
    uint32_t a;
    asm("{ .reg .u64 t; cvta.to.shared.u64 t, %1; cvt.u32.u64 %0, t; }" : "=r"(a) : "l"(p));
    return a;
}
__device__ __forceinline__ uint32_t f2tf32(float x) {
    uint32_t r; asm("cvt.rna.tf32.f32 %0, %1;" : "=r"(r) : "f"(x)); return r;
}
// Swizzle<3,4,3>
__device__ __forceinline__ uint32_t swz(uint32_t off) {
    return off ^ ((off >> 3) & 0x70);
}
__device__ __forceinline__ void cp_async16(uint32_t dst, const void* src) {
    asm volatile("cp.async.cg.shared.global [%0], [%1], 16;" :: "r"(dst), "l"(src));
}
__device__ __forceinline__ void cp_commit() {
    asm volatile("cp.async.commit_group;" ::: "memory");
}
template <int N>
__device__ __forceinline__ void cp_wait() {
    asm volatile("cp.async.wait_group %0;" :: "n"(N) : "memory");
}
__device__ __forceinline__ void ldmatrix_x4(uint32_t& r0, uint32_t& r1, uint32_t& r2, uint32_t& r3,
                                            uint32_t addr) {
    asm volatile("ldmatrix.sync.aligned.m8n8.x4.shared.b16 {%0,%1,%2,%3}, [%4];"
                 : "=r"(r0), "=r"(r1), "=r"(r2), "=r"(r3) : "r"(addr));
}
__device__ __forceinline__ void mma_tf32(float& c0, float& c1, float& c2, float& c3,
                                         uint32_t a0, uint32_t a1, uint32_t a2, uint32_t a3,
                                         uint32_t b0, uint32_t b1) {
    asm volatile("mma.sync.aligned.m16n8k8.row.col.f32.tf32.tf32.f32 "
                 "{%0,%1,%2,%3}, {%4,%5,%6,%7}, {%8,%9}, {%0,%1,%2,%3};"
                 : "+f"(c0), "+f"(c1), "+f"(c2), "+f"(c3)
                 : "r"(a0), "r"(a1), "r"(a2), "r"(a3), "r"(b0), "r"(b1));
}

// -------------------- tf32 pre-conversion (weights only; tiny) --------------------
__global__ __launch_bounds__(256)
void cvt_tf32_kernel(const float* __restrict__ in, float* __restrict__ out, int n4) {
    int i = blockIdx.x * blockDim.x + threadIdx.x;
    if (i < n4) {
        float4 v = ((const float4*)in)[i];
        uint4 o;
        o.x = f2tf32(v.x); o.y = f2tf32(v.y);
        o.z = f2tf32(v.z); o.w = f2tf32(v.w);
        ((uint4*)out)[i] = o;
    }
}

// -------------------- tf32 mma.sync GEMM (R9 config: 128x128, 256thr, occ 2) ----
// C[m,n] = sum_k A[m,k]*B[n,k] (+bias[n]); M=65536, N=256, K=256.
// STAGE_A=true: A staged LDG -> tf32-cvt -> STS (for raw-fp32 A = x); cvt is off
// the ldmatrix->mma critical path and LDG latency hides under the kt's mma work.
// STAGE_A=false: A staged via cp.async (A already tf32-rounded bits).
// B always via cp.async (pre-rounded weights).
#define GEMM_BM 128
#define GEMM_BN 128
#define GEMM_BK 32
#define TILE_BYTES (128 * 32 * 4)          // 16 KB
#define BUF_BYTES  (2 * TILE_BYTES)        // A+B per stage = 32 KB
#define NSTAGE 3
#define DSMEM_BYTES (NSTAGE * BUF_BYTES)   // 96 KB
#define NKT (CC / GEMM_BK)                 // 8

template <bool STAGE_A>
__global__ __launch_bounds__(256, 2)
void gemm_tf32_mma_kernel(const float* __restrict__ A,
                          const float* __restrict__ Bw,
                          const float* __restrict__ bias,
                          float* __restrict__ C)
{
    extern __shared__ char sm[];
    const int tid = threadIdx.x;
    const int wid = tid >> 5;
    const int lane = tid & 31;
    const int warp_m = wid >> 2;
    const int warp_n = wid & 3;
    const int bm = blockIdx.y * GEMM_BM;
    const int bn = blockIdx.x * GEMM_BN;

    const uint32_t smbase = smem_u32(sm);

    const int st_c4  = tid & 7;
    const int st_row0 = tid >> 3;
    uint32_t st_off[4];
    #pragma unroll
    for (int i = 0; i < 4; i++)
        st_off[i] = swz((uint32_t)(st_row0 + 32 * i) * 128 + st_c4 * 16);

    const float* Abase = A + (size_t)(bm + st_row0) * CC + st_c4 * 4;
    const float* Bbase = Bw + (size_t)(bn + st_row0) * CC + st_c4 * 4;

    // prologue: stages 0 and 1
    #pragma unroll
    for (int s = 0; s < 2; s++) {
        const uint32_t buf = smbase + s * BUF_BYTES;
        char* dst = sm + s * BUF_BYTES;
        #pragma unroll
        for (int i = 0; i < 4; i++) {
            if (STAGE_A) {
                float4 t = *(const float4*)(Abase + (size_t)i * 32 * CC + s * GEMM_BK);
                uint4 u;
                u.x = f2tf32(t.x); u.y = f2tf32(t.y);
                u.z = f2tf32(t.z); u.w = f2tf32(t.w);
                *(uint4*)(dst + st_off[i]) = u;
            } else {
                cp_async16(buf + st_off[i], Abase + (size_t)i * 32 * CC + s * GEMM_BK);
            }
            cp_async16(buf + TILE_BYTES + st_off[i], Bbase + (size_t)i * 32 * CC + s * GEMM_BK);
        }
        cp_commit();
    }

    float acc[4][4][4];
    #pragma unroll
    for (int mt = 0; mt < 4; mt++)
        #pragma unroll
        for (int nt = 0; nt < 4; nt++)
            #pragma unroll
            for (int r = 0; r < 4; r++)
                acc[mt][nt][r] = 0.0f;

    const int a_row_in = (lane & 7) + ((lane >> 3) & 1) * 8;
    const int a_chunk_hi = (lane >> 4);
    const int b_nt_off = (lane >> 4) * 8;
    const int b_row_in = (lane & 7);
    const int b_chunk_hi = (lane >> 3) & 1;

    #pragma unroll
    for (int kt = 0; kt < NKT; kt++) {
        if (kt + 1 < NKT) cp_wait<1>(); else cp_wait<0>();
        __syncthreads();

        float4 pa[4];
        if (kt + 2 < NKT) {
            const uint32_t buf = smbase + ((kt + 2) % NSTAGE) * BUF_BYTES;
            #pragma unroll
            for (int i = 0; i < 4; i++) {
                if (STAGE_A) {
                    pa[i] = *(const float4*)(Abase + (size_t)i * 32 * CC + (kt + 2) * GEMM_BK);
                } else {
                    cp_async16(buf + st_off[i], Abase + (size_t)i * 32 * CC + (kt + 2) * GEMM_BK);
                }
                cp_async16(buf + TILE_BYTES + st_off[i], Bbase + (size_t)i * 32 * CC + (kt + 2) * GEMM_BK);
            }
            cp_commit();
        }

        const uint32_t abuf = smbase + (kt % NSTAGE) * BUF_BYTES;
        const uint32_t bbuf = abuf + TILE_BYTES;

        #pragma unroll
        for (int kk = 0; kk < 4; kk++) {
            uint32_t af[4][4];
            #pragma unroll
            for (int mt = 0; mt < 4; mt++) {
                const int row = warp_m * 64 + mt * 16 + a_row_in;
                const uint32_t off = swz((uint32_t)row * 128 + (kk * 2 + a_chunk_hi) * 16);
                ldmatrix_x4(af[mt][0], af[mt][1], af[mt][2], af[mt][3], abuf + off);
            }
            uint32_t bf[4][2];
            #pragma unroll
            for (int pair = 0; pair < 2; pair++) {
                const int row = warp_n * 32 + pair * 16 + b_nt_off + b_row_in;
                const uint32_t off = swz((uint32_t)row * 128 + (kk * 2 + b_chunk_hi) * 16);
                uint32_t r0, r1, r2, r3;
                ldmatrix_x4(r0, r1, r2, r3, bbuf + off);
                bf[pair * 2 + 0][0] = r0; bf[pair * 2 + 0][1] = r1;
                bf[pair * 2 + 1][0] = r2; bf[pair * 2 + 1][1] = r3;
            }
            #pragma unroll
            for (int mt = 0; mt < 4; mt++)
                #pragma unroll
                for (int nt = 0; nt < 4; nt++)
                    mma_tf32(acc[mt][nt][0], acc[mt][nt][1], acc[mt][nt][2], acc[mt][nt][3],
                             af[mt][0], af[mt][1], af[mt][2], af[mt][3],
                             bf[nt][0], bf[nt][1]);
        }

        // A STS for stage kt+2 AFTER compute: target buffer ((kt+2)%3 == (kt-1)%3)
        // finished its compute before this kt's top barrier; consumers of this
        // data run after the kt+2 top barrier.
        if (STAGE_A && kt + 2 < NKT) {
            char* dst = sm + ((kt + 2) % NSTAGE) * BUF_BYTES;
            #pragma unroll
            for (int i = 0; i < 4; i++) {
                uint4 u;
                u.x = f2tf32(pa[i].x); u.y = f2tf32(pa[i].y);
                u.z = f2tf32(pa[i].z); u.w = f2tf32(pa[i].w);
                *(uint4*)(dst + st_off[i]) = u;
            }
        }
    }

    // epilogue
    const int er = warp_m * 64 + (lane >> 2);
    const int ec = warp_n * 32 + (lane & 3) * 2;
    #pragma unroll
    for (int mt = 0; mt < 4; mt++) {
        #pragma unroll
        for (int nt = 0; nt < 4; nt++) {
            const int row = bm + er + mt * 16;
            const int col = bn + ec + nt * 8;
            float2 lo = make_float2(acc[mt][nt][0], acc[mt][nt][1]);
            float2 hi = make_float2(acc[mt][nt][2], acc[mt][nt][3]);
            if (bias) {
                const float b0 = bias[col], b1 = bias[col + 1];
                lo.x += b0; lo.y += b1; hi.x += b0; hi.y += b1;
            }
            *(float2*)(C + (size_t)row * CC + col)       = lo;
            *(float2*)(C + (size_t)(row + 8) * CC + col) = hi;
        }
    }
}

// -------------------- flow-guided gather + aggregation (R9 v3) -----
// Block = (hd, t, 16x16 h/w tile), 256 threads.
__global__ __launch_bounds__(256)
void gather_agg_kernel(const float* __restrict__ v,
                       const float* __restrict__ attn,
                       const int*   __restrict__ flows,
                       float* __restrict__ agg)
{
    __shared__ float s_attn[256 * KNBR];        // 9 KB, layout [pl*9 + k]
    __shared__ int   s_flows[256 * KNBR * 3];   // 27 KB
    __shared__ int   s_voff[256 * KNBR];        // 9 KB

    int b = blockIdx.x;
    const int w0 = (b & 7) << 4; b >>= 3;
    const int h0 = (b & 7) << 4; b >>= 3;
    const int t  = b & 3;
    const int hd = b >> 2;

    const int tid = threadIdx.x;

    // ---- stage 0: coalesced staging (16 row-segments) ----
    const size_t pos00 = ((size_t)((hd * TT + t) * HH + h0)) * WW + w0;
    {
        const float* ab = attn + pos00 * KNBR;
        #pragma unroll
        for (int j = tid; j < 16 * 144; j += 256) {      // 9 iters
            const int r = j / 144;
            const int c = j - r * 144;
            s_attn[r * 144 + c] = __ldg(ab + (size_t)r * (WW * KNBR) + c);
        }
        const int* fb = flows + pos00 * (KNBR * 3);
        #pragma unroll
        for (int j = tid; j < 16 * 432; j += 256) {      // 27 iters
            const int r = j / 432;
            const int c = j - r * 432;
            s_flows[r * 432 + c] = __ldg(fb + (size_t)r * (WW * KNBR * 3) + c);
        }
    }
    __syncthreads();

    // ---- stage 1: clipped v-row offsets ----
    {
        const int pl = tid;
        const int w = w0 + (pl & 15);
        const int h = h0 + (pl >> 4);
        #pragma unroll
        for (int k = 0; k < KNBR; k++) {
            const int dt = s_flows[pl * 27 + k * 3 + 0];
            const int dh = s_flows[pl * 27 + k * 3 + 1];
            const int dw = s_flows[pl * 27 + k * 3 + 2];
            const int tt = min(max(t + dt, 0), TT - 1);
            const int hh = min(max(h + dh, 0), HH - 1);
            const int ww = min(max(w + dw, 0), WW - 1);
            s_voff[pl * KNBR + k] = ((tt * HH + hh) * WW + ww) * CC;
        }
    }
    __syncthreads();

    // ---- stage 2: gather + weighted sum ----
    const int fbyte = hd * FF;
    #pragma unroll
    for (int i = 0; i < 8; i++) {
        const int item = tid + (i << 8);      // 0..2047
        const int fq = item & 7;
        const int pl = item >> 3;             // 0..255
        const int w = w0 + (pl & 15);
        const int h = h0 + (pl >> 4);

        float4 acc = make_float4(0.f, 0.f, 0.f, 0.f);
        #pragma unroll
        for (int k = 0; k < KNBR; k++) {
            const float wk = s_attn[pl * KNBR + k];
            const int voff = s_voff[pl * KNBR + k];
            const float4 vv = *(const float4*)(v + voff + fbyte + fq * 4);
            acc.x += wk * vv.x; acc.y += wk * vv.y;
            acc.z += wk * vv.z; acc.w += wk * vv.w;
        }
        uint4 o;
        o.x = f2tf32(acc.x); o.y = f2tf32(acc.y);
        o.z = f2tf32(acc.z); o.w = f2tf32(acc.w);
        *(uint4*)(agg + ((size_t)((t * HH + h) * WW + w)) * CC + fbyte + fq * 4) = o;
    }
}

// -------------------- launch --------------------
extern "C" void kernel_launch(void* const* d_in, const int* in_sizes, int n_in,
                              void* d_out, int out_size)
{
    const float* x      = (const float*)d_in[0];
    const float* attn   = (const float*)d_in[1];
    const int*   flows  = (const int*)  d_in[2];
    const float* v_w    = (const float*)d_in[3];
    const float* proj_w = (const float*)d_in[4];
    const float* proj_b = (const float*)d_in[5];
    float* out = (float*)d_out;

    float *v_buf, *agg_buf, *wv, *wp;
    cudaGetSymbolAddress((void**)&v_buf,   g_v);
    cudaGetSymbolAddress((void**)&agg_buf, g_agg);
    cudaGetSymbolAddress((void**)&wv,      g_wv);
    cudaGetSymbolAddress((void**)&wp,      g_wp);

    cudaFuncSetAttribute(gemm_tf32_mma_kernel<true>,
                         cudaFuncAttributeMaxDynamicSharedMemorySize, DSMEM_BYTES);
    cudaFuncSetAttribute(gemm_tf32_mma_kernel<false>,
                         cudaFuncAttributeMaxDynamicSharedMemorySize, DSMEM_BYTES);

    // 0) pre-round weights (tiny: 2 x 256KB)
    {
        const int n4w = CC * CC / 4;   // 16384
        cvt_tf32_kernel<<<n4w / 256, 256>>>(v_w, wv, n4w);
        cvt_tf32_kernel<<<n4w / 256, 256>>>(proj_w, wp, n4w);
    }

    dim3 ggrid(CC / GEMM_BN, MDIM / GEMM_BM);   // (2, 512)

    // 1) v = x @ v_w.T   (A staged LDG->cvt->STS; B pre-rounded via cp.async)
    gemm_tf32_mma_kernel<true><<<ggrid, 256, DSMEM_BYTES>>>(x, wv, nullptr, v_buf);

    // 2) gather + weighted aggregation (R9 v3; emits tf32-rounded agg)
    {
        const int blocks = HDN * TT * 8 * 8;     // 2048
        gather_agg_kernel<<<blocks, 256>>>(v_buf, attn, flows, agg_buf);
    }

    // 3) out = agg @ proj_w.T + proj_b  (both operands pre-rounded; all cp.async)
    gemm_tf32_mma_kernel<false><<<ggrid, 256, DSMEM_BYTES>>>(agg_buf, wp, proj_b, out);
}

// round 13
// speedup vs baseline: 1.2336x; 1.0480x over previous
#include <cuda_runtime.h>
#include <cstdint>

// -------------------- problem constants --------------------
#define TT   4
#define HH   128
#define WW   128
#define CC   256
#define HDN  8
#define KNBR 9
#define FF   32
#define MDIM (TT*HH*WW)   // 65536

// scratch (device globals; no runtime allocation allowed)
__device__ float g_v[(size_t)MDIM * CC];     // v = x @ v_w.T (fp32)
__device__ float g_agg[(size_t)MDIM * CC];   // aggregated (tf32-rounded bits)
__device__ float g_wv[(size_t)CC * CC];      // v_w tf32-rounded
__device__ float g_wp[(size_t)CC * CC];      // proj_w tf32-rounded

// -------------------- helpers --------------------
__device__ __forceinline__ uint32_t smem_u32(const void* p) {
    uint32_t a;
    asm("{ .reg .u64 t; cvta.to.shared.u64 t, %1; cvt.u32.u64 %0, t; }" : "=r"(a) : "l"(p));
    return a;
}
__device__ __forceinline__ uint32_t f2tf32(float x) {
    uint32_t r; asm("cvt.rna.tf32.f32 %0, %1;" : "=r"(r) : "f"(x)); return r;
}
__device__ __forceinline__ uint32_t rnd_u(uint32_t u) {
    uint32_t r; asm("cvt.rna.tf32.f32 %0, %1;" : "=r"(r) : "f"(__uint_as_float(u))); return r;
}
// Swizzle<3,4,3>
__device__ __forceinline__ uint32_t swz(uint32_t off) {
    return off ^ ((off >> 3) & 0x70);
}
__device__ __forceinline__ void cp_async16(uint32_t dst, const void* src) {
    asm volatile("cp.async.cg.shared.global [%0], [%1], 16;" :: "r"(dst), "l"(src));
}
__device__ __forceinline__ void cp_commit() {
    asm volatile("cp.async.commit_group;" ::: "memory");
}
template <int N>
__device__ __forceinline__ void cp_wait() {
    asm volatile("cp.async.wait_group %0;" :: "n"(N) : "memory");
}
__device__ __forceinline__ void ldmatrix_x4(uint32_t& r0, uint32_t& r1, uint32_t& r2, uint32_t& r3,
                                            uint32_t addr) {
    asm volatile("ldmatrix.sync.aligned.m8n8.x4.shared.b16 {%0,%1,%2,%3}, [%4];"
                 : "=r"(r0), "=r"(r1), "=r"(r2), "=r"(r3) : "r"(addr));
}
__device__ __forceinline__ void mma_tf32(float& c0, float& c1, float& c2, float& c3,
                                         uint32_t a0, uint32_t a1, uint32_t a2, uint32_t a3,
                                         uint32_t b0, uint32_t b1) {
    asm volatile("mma.sync.aligned.m16n8k8.row.col.f32.tf32.tf32.f32 "
                 "{%0,%1,%2,%3}, {%4,%5,%6,%7}, {%8,%9}, {%0,%1,%2,%3};"
                 : "+f"(c0), "+f"(c1), "+f"(c2), "+f"(c3)
                 : "r"(a0), "r"(a1), "r"(a2), "r"(a3), "r"(b0), "r"(b1));
}

// -------------------- tf32 pre-conversion (weights only; tiny) --------------------
__global__ __launch_bounds__(256)
void cvt_tf32_kernel(const float* __restrict__ in, float* __restrict__ out, int n4) {
    int i = blockIdx.x * blockDim.x + threadIdx.x;
    if (i < n4) {
        float4 v = ((const float4*)in)[i];
        uint4 o;
        o.x = f2tf32(v.x); o.y = f2tf32(v.y);
        o.z = f2tf32(v.z); o.w = f2tf32(v.w);
        ((uint4*)out)[i] = o;
    }
}

// -------------------- tf32 mma.sync GEMM (R9: cp.async 3-stage, 128x128) ------
// CVT_A / CVT_B: round the respective ldmatrix fragments f32->tf32 (RNA) in-register.
#define GEMM_BM 128
#define GEMM_BN 128
#define GEMM_BK 32
#define TILE_BYTES (128 * 32 * 4)          // 16 KB
#define BUF_BYTES  (2 * TILE_BYTES)        // A+B per stage = 32 KB
#define NSTAGE 3
#define DSMEM_BYTES (NSTAGE * BUF_BYTES)   // 96 KB
#define NKT (CC / GEMM_BK)                 // 8

template <bool CVT_A, bool CVT_B>
__global__ __launch_bounds__(256, 2)
void gemm_tf32_mma_kernel(const float* __restrict__ A,
                          const float* __restrict__ Bw,
                          const float* __restrict__ bias,
                          float* __restrict__ C)
{
    extern __shared__ char sm[];
    const int tid = threadIdx.x;
    const int wid = tid >> 5;
    const int lane = tid & 31;
    const int warp_m = wid >> 2;
    const int warp_n = wid & 3;
    const int bm = blockIdx.y * GEMM_BM;
    const int bn = blockIdx.x * GEMM_BN;

    const uint32_t smbase = smem_u32(sm);

    const int st_c4  = tid & 7;
    const int st_row0 = tid >> 3;
    uint32_t st_off[4];
    #pragma unroll
    for (int i = 0; i < 4; i++)
        st_off[i] = swz((uint32_t)(st_row0 + 32 * i) * 128 + st_c4 * 16);

    const float* Abase = A + (size_t)(bm + st_row0) * CC + st_c4 * 4;
    const float* Bbase = Bw + (size_t)(bn + st_row0) * CC + st_c4 * 4;

    #pragma unroll
    for (int s = 0; s < 2; s++) {
        const uint32_t buf = smbase + s * BUF_BYTES;
        #pragma unroll
        for (int i = 0; i < 4; i++) {
            cp_async16(buf + st_off[i],              Abase + (size_t)i * 32 * CC + s * GEMM_BK);
            cp_async16(buf + TILE_BYTES + st_off[i], Bbase + (size_t)i * 32 * CC + s * GEMM_BK);
        }
        cp_commit();
    }

    float acc[4][4][4];
    #pragma unroll
    for (int mt = 0; mt < 4; mt++)
        #pragma unroll
        for (int nt = 0; nt < 4; nt++)
            #pragma unroll
            for (int r = 0; r < 4; r++)
                acc[mt][nt][r] = 0.0f;

    const int a_row_in = (lane & 7) + ((lane >> 3) & 1) * 8;
    const int a_chunk_hi = (lane >> 4);
    const int b_nt_off = (lane >> 4) * 8;
    const int b_row_in = (lane & 7);
    const int b_chunk_hi = (lane >> 3) & 1;

    #pragma unroll
    for (int kt = 0; kt < NKT; kt++) {
        if (kt + 1 < NKT) cp_wait<1>(); else cp_wait<0>();
        __syncthreads();
        if (kt + 2 < NKT) {
            const uint32_t buf = smbase + ((kt + 2) % NSTAGE) * BUF_BYTES;
            #pragma unroll
            for (int i = 0; i < 4; i++) {
                cp_async16(buf + st_off[i],              Abase + (size_t)i * 32 * CC + (kt + 2) * GEMM_BK);
                cp_async16(buf + TILE_BYTES + st_off[i], Bbase + (size_t)i * 32 * CC + (kt + 2) * GEMM_BK);
            }
            cp_commit();
        }

        const uint32_t abuf = smbase + (kt % NSTAGE) * BUF_BYTES;
        const uint32_t bbuf = abuf + TILE_BYTES;

        #pragma unroll
        for (int kk = 0; kk < 4; kk++) {
            uint32_t af[4][4];
            #pragma unroll
            for (int mt = 0; mt < 4; mt++) {
                const int row = warp_m * 64 + mt * 16 + a_row_in;
                const uint32_t off = swz((uint32_t)row * 128 + (kk * 2 + a_chunk_hi) * 16);
                ldmatrix_x4(af[mt][0], af[mt][1], af[mt][2], af[mt][3], abuf + off);
                if (CVT_A) {
                    af[mt][0] = rnd_u(af[mt][0]); af[mt][1] = rnd_u(af[mt][1]);
                    af[mt][2] = rnd_u(af[mt][2]); af[mt][3] = rnd_u(af[mt][3]);
                }
            }
            uint32_t bf[4][2];
            #pragma unroll
            for (int pair = 0; pair < 2; pair++) {
                const int row = warp_n * 32 + pair * 16 + b_nt_off + b_row_in;
                const uint32_t off = swz((uint32_t)row * 128 + (kk * 2 + b_chunk_hi) * 16);
                uint32_t r0, r1, r2, r3;
                ldmatrix_x4(r0, r1, r2, r3, bbuf + off);
                if (CVT_B) {
                    r0 = rnd_u(r0); r1 = rnd_u(r1); r2 = rnd_u(r2); r3 = rnd_u(r3);
                }
                bf[pair * 2 + 0][0] = r0; bf[pair * 2 + 0][1] = r1;
                bf[pair * 2 + 1][0] = r2; bf[pair * 2 + 1][1] = r3;
            }
            #pragma unroll
            for (int mt = 0; mt < 4; mt++)
                #pragma unroll
                for (int nt = 0; nt < 4; nt++)
                    mma_tf32(acc[mt][nt][0], acc[mt][nt][1], acc[mt][nt][2], acc[mt][nt][3],
                             af[mt][0], af[mt][1], af[mt][2], af[mt][3],
                             bf[nt][0], bf[nt][1]);
        }
    }

    // epilogue
    const int er = warp_m * 64 + (lane >> 2);
    const int ec = warp_n * 32 + (lane & 3) * 2;
    #pragma unroll
    for (int mt = 0; mt < 4; mt++) {
        #pragma unroll
        for (int nt = 0; nt < 4; nt++) {
            const int row = bm + er + mt * 16;
            const int col = bn + ec + nt * 8;
            float2 lo = make_float2(acc[mt][nt][0], acc[mt][nt][1]);
            float2 hi = make_float2(acc[mt][nt][2], acc[mt][nt][3]);
            if (bias) {
                const float b0 = bias[col], b1 = bias[col + 1];
                lo.x += b0; lo.y += b1; hi.x += b0; hi.y += b1;
            }
            *(float2*)(C + (size_t)row * CC + col)       = lo;
            *(float2*)(C + (size_t)(row + 8) * CC + col) = hi;
        }
    }
}

// -------------------- flow-guided gather + aggregation (v3 + hoisted stage 2) --
// Block = (hd, t, 16x16 h/w tile), 256 threads. smem identical to R9 (45 KB,
// ~4 CTAs/SM — the locality sweet spot); only stage-2 index math is hoisted.
__global__ __launch_bounds__(256)
void gather_agg_kernel(const float* __restrict__ v,
                       const float* __restrict__ attn,
                       const int*   __restrict__ flows,
                       float* __restrict__ agg)
{
    __shared__ float s_attn[256 * KNBR];        // 9 KB, layout [pl*9 + k]
    __shared__ int   s_flows[256 * KNBR * 3];   // 27 KB
    __shared__ int   s_voff[256 * KNBR];        // 9 KB

    int b = blockIdx.x;
    const int w0 = (b & 7) << 4; b >>= 3;
    const int h0 = (b & 7) << 4; b >>= 3;
    const int t  = b & 3;
    const int hd = b >> 2;

    const int tid = threadIdx.x;

    // ---- stage 0: coalesced staging (16 row-segments) ----
    const size_t pos00 = ((size_t)((hd * TT + t) * HH + h0)) * WW + w0;
    {
        const float* ab = attn + pos00 * KNBR;
        #pragma unroll
        for (int j = tid; j < 16 * 144; j += 256) {      // 9 iters
            const int r = j / 144;
            const int c = j - r * 144;
            s_attn[r * 144 + c] = __ldg(ab + (size_t)r * (WW * KNBR) + c);
        }
        const int* fb = flows + pos00 * (KNBR * 3);
        #pragma unroll
        for (int j = tid; j < 16 * 432; j += 256) {      // 27 iters
            const int r = j / 432;
            const int c = j - r * 432;
            s_flows[r * 432 + c] = __ldg(fb + (size_t)r * (WW * KNBR * 3) + c);
        }
    }
    __syncthreads();

    // ---- stage 1: clipped v-row offsets ----
    {
        const int pl = tid;
        const int w = w0 + (pl & 15);
        const int h = h0 + (pl >> 4);
        #pragma unroll
        for (int k = 0; k < KNBR; k++) {
            const int dt = s_flows[pl * 27 + k * 3 + 0];
            const int dh = s_flows[pl * 27 + k * 3 + 1];
            const int dw = s_flows[pl * 27 + k * 3 + 2];
            const int tt = min(max(t + dt, 0), TT - 1);
            const int hh = min(max(h + dh, 0), HH - 1);
            const int ww = min(max(w + dw, 0), WW - 1);
            s_voff[pl * KNBR + k] = ((tt * HH + hh) * WW + ww) * CC;
        }
    }
    __syncthreads();

    // ---- stage 2: gather + weighted sum (i-invariant indexing hoisted) ----
    // item = tid + 256*i  =>  fq = tid&7 (invariant), pl = (tid>>3) + 32*i
    // pl&15 (w) invariant; pl>>4 advances by 2 per i  =>  out ptr += 2*WW*CC.
    const int fq  = tid & 7;
    const int pl0 = tid >> 3;                // 0..31
    const int fbyte = hd * FF + fq * 4;
    const float* vb = v + fbyte;
    float* op = agg + ((size_t)((t * HH + (h0 + (pl0 >> 4))) * WW + (w0 + (pl0 & 15)))) * CC + fbyte;
    int sb = pl0 * KNBR;

    #pragma unroll
    for (int i = 0; i < 8; i++) {
        float4 acc = make_float4(0.f, 0.f, 0.f, 0.f);
        #pragma unroll
        for (int k = 0; k < KNBR; k++) {
            const float wk = s_attn[sb + k];
            const int voff = s_voff[sb + k];
            const float4 vv = *(const float4*)(vb + voff);
            acc.x += wk * vv.x; acc.y += wk * vv.y;
            acc.z += wk * vv.z; acc.w += wk * vv.w;
        }
        uint4 o;
        o.x = f2tf32(acc.x); o.y = f2tf32(acc.y);
        o.z = f2tf32(acc.z); o.w = f2tf32(acc.w);
        *(uint4*)op = o;
        sb += 32 * KNBR;                 // next 32 positions
        op += (size_t)2 * WW * CC;       // +2 h-rows
    }
}

// -------------------- launch --------------------
extern "C" void kernel_launch(void* const* d_in, const int* in_sizes, int n_in,
                              void* d_out, int out_size)
{
    const float* x      = (const float*)d_in[0];
    const float* attn   = (const float*)d_in[1];
    const int*   flows  = (const int*)  d_in[2];
    const float* v_w    = (const float*)d_in[3];
    const float* proj_w = (const float*)d_in[4];
    const float* proj_b = (const float*)d_in[5];
    float* out = (float*)d_out;

    float *v_buf, *agg_buf, *wv, *wp;
    cudaGetSymbolAddress((void**)&v_buf,   g_v);
    cudaGetSymbolAddress((void**)&agg_buf, g_agg);
    cudaGetSymbolAddress((void**)&wv,      g_wv);
    cudaGetSymbolAddress((void**)&wp,      g_wp);

    cudaFuncSetAttribute(gemm_tf32_mma_kernel<true, false>,
                         cudaFuncAttributeMaxDynamicSharedMemorySize, DSMEM_BYTES);
    cudaFuncSetAttribute(gemm_tf32_mma_kernel<false, false>,
                         cudaFuncAttributeMaxDynamicSharedMemorySize, DSMEM_BYTES);

    // 0) pre-round weights (tiny: 2 x 256KB)
    {
        const int n4w = CC * CC / 4;   // 16384
        cvt_tf32_kernel<<<n4w / 256, 256>>>(v_w, wv, n4w);
        cvt_tf32_kernel<<<n4w / 256, 256>>>(proj_w, wp, n4w);
    }

    dim3 ggrid(CC / GEMM_BN, MDIM / GEMM_BM);   // (2, 512)

    // 1) v = x @ v_w.T   (A rounded in-register — best measured variant; B pre-rounded)
    gemm_tf32_mma_kernel<true, false><<<ggrid, 256, DSMEM_BYTES>>>(x, wv, nullptr, v_buf);

    // 2) gather + weighted aggregation
    {
        const int blocks = HDN * TT * 8 * 8;     // 2048
        gather_agg_kernel<<<blocks, 256>>>(v_buf, attn, flows, agg_buf);
    }

    // 3) out = agg @ proj_w.T + proj_b  (both operands pre-rounded)
    gemm_tf32_mma_kernel<false, false><<<ggrid, 256, DSMEM_BYTES>>>(agg_buf, wp, proj_b, out);
}

// round 14
// speedup vs baseline: 1.2339x; 1.0002x over previous
#include <cuda_runtime.h>
#include <cstdint>

// -------------------- problem constants --------------------
#define TT   4
#define HH   128
#define WW   128
#define CC   256
#define HDN  8
#define KNBR 9
#define FF   32
#define MDIM (TT*HH*WW)   // 65536

// scratch (device globals; no runtime allocation allowed)
__device__ float g_v[(size_t)MDIM * CC];     // v = x @ v_w.T (fp32)
__device__ float g_agg[(size_t)MDIM * CC];   // aggregated (tf32-rounded bits)
__device__ float g_wv[(size_t)CC * CC];      // v_w tf32-rounded
__device__ float g_wp[(size_t)CC * CC];      // proj_w tf32-rounded

// -------------------- helpers --------------------
__device__ __forceinline__ uint32_t smem_u32(const void* p) {
    uint32_t a;
    asm("{ .reg .u64 t; cvta.to.shared.u64 t, %1; cvt.u32.u64 %0, t; }" : "=r"(a) : "l"(p));
    return a;
}
__device__ __forceinline__ uint32_t f2tf32(float x) {
    uint32_t r; asm("cvt.rna.tf32.f32 %0, %1;" : "=r"(r) : "f"(x)); return r;
}
__device__ __forceinline__ uint32_t rnd_u(uint32_t u) {
    uint32_t r; asm("cvt.rna.tf32.f32 %0, %1;" : "=r"(r) : "f"(__uint_as_float(u))); return r;
}
// Swizzle<3,4,3>
__device__ __forceinline__ uint32_t swz(uint32_t off) {
    return off ^ ((off >> 3) & 0x70);
}
__device__ __forceinline__ void cp_async16(uint32_t dst, const void* src) {
    asm volatile("cp.async.cg.shared.global [%0], [%1], 16;" :: "r"(dst), "l"(src));
}
__device__ __forceinline__ void cp_commit() {
    asm volatile("cp.async.commit_group;" ::: "memory");
}
template <int N>
__device__ __forceinline__ void cp_wait() {
    asm volatile("cp.async.wait_group %0;" :: "n"(N) : "memory");
}
__device__ __forceinline__ void ldmatrix_x4(uint32_t& r0, uint32_t& r1, uint32_t& r2, uint32_t& r3,
                                            uint32_t addr) {
    asm volatile("ldmatrix.sync.aligned.m8n8.x4.shared.b16 {%0,%1,%2,%3}, [%4];"
                 : "=r"(r0), "=r"(r1), "=r"(r2), "=r"(r3) : "r"(addr));
}
__device__ __forceinline__ void mma_tf32(float& c0, float& c1, float& c2, float& c3,
                                         uint32_t a0, uint32_t a1, uint32_t a2, uint32_t a3,
                                         uint32_t b0, uint32_t b1) {
    asm volatile("mma.sync.aligned.m16n8k8.row.col.f32.tf32.tf32.f32 "
                 "{%0,%1,%2,%3}, {%4,%5,%6,%7}, {%8,%9}, {%0,%1,%2,%3};"
                 : "+f"(c0), "+f"(c1), "+f"(c2), "+f"(c3)
                 : "r"(a0), "r"(a1), "r"(a2), "r"(a3), "r"(b0), "r"(b1));
}

// -------------------- tf32 pre-conversion (weights only; tiny) --------------------
__global__ __launch_bounds__(256)
void cvt_tf32_kernel(const float* __restrict__ in, float* __restrict__ out, int n4) {
    int i = blockIdx.x * blockDim.x + threadIdx.x;
    if (i < n4) {
        float4 v = ((const float4*)in)[i];
        uint4 o;
        o.x = f2tf32(v.x); o.y = f2tf32(v.y);
        o.z = f2tf32(v.z); o.w = f2tf32(v.w);
        ((uint4*)out)[i] = o;
    }
}

// -------------------- tf32 mma.sync GEMM (R9: cp.async 3-stage, 128x128) ------
// CVT_A / CVT_B: round the respective ldmatrix fragments f32->tf32 (RNA) in-register.
#define GEMM_BM 128
#define GEMM_BN 128
#define GEMM_BK 32
#define TILE_BYTES (128 * 32 * 4)          // 16 KB
#define BUF_BYTES  (2 * TILE_BYTES)        // A+B per stage = 32 KB
#define NSTAGE 3
#define DSMEM_BYTES (NSTAGE * BUF_BYTES)   // 96 KB
#define NKT (CC / GEMM_BK)                 // 8

template <bool CVT_A, bool CVT_B>
__global__ __launch_bounds__(256, 2)
void gemm_tf32_mma_kernel(const float* __restrict__ A,
                          const float* __restrict__ Bw,
                          const float* __restrict__ bias,
                          float* __restrict__ C)
{
    extern __shared__ char sm[];
    const int tid = threadIdx.x;
    const int wid = tid >> 5;
    const int lane = tid & 31;
    const int warp_m = wid >> 2;
    const int warp_n = wid & 3;
    const int bm = blockIdx.y * GEMM_BM;
    const int bn = blockIdx.x * GEMM_BN;

    const uint32_t smbase = smem_u32(sm);

    const int st_c4  = tid & 7;
    const int st_row0 = tid >> 3;
    uint32_t st_off[4];
    #pragma unroll
    for (int i = 0; i < 4; i++)
        st_off[i] = swz((uint32_t)(st_row0 + 32 * i) * 128 + st_c4 * 16);

    const float* Abase = A + (size_t)(bm + st_row0) * CC + st_c4 * 4;
    const float* Bbase = Bw + (size_t)(bn + st_row0) * CC + st_c4 * 4;

    #pragma unroll
    for (int s = 0; s < 2; s++) {
        const uint32_t buf = smbase + s * BUF_BYTES;
        #pragma unroll
        for (int i = 0; i < 4; i++) {
            cp_async16(buf + st_off[i],              Abase + (size_t)i * 32 * CC + s * GEMM_BK);
            cp_async16(buf + TILE_BYTES + st_off[i], Bbase + (size_t)i * 32 * CC + s * GEMM_BK);
        }
        cp_commit();
    }

    float acc[4][4][4];
    #pragma unroll
    for (int mt = 0; mt < 4; mt++)
        #pragma unroll
        for (int nt = 0; nt < 4; nt++)
            #pragma unroll
            for (int r = 0; r < 4; r++)
                acc[mt][nt][r] = 0.0f;

    const int a_row_in = (lane & 7) + ((lane >> 3) & 1) * 8;
    const int a_chunk_hi = (lane >> 4);
    const int b_nt_off = (lane >> 4) * 8;
    const int b_row_in = (lane & 7);
    const int b_chunk_hi = (lane >> 3) & 1;

    #pragma unroll
    for (int kt = 0; kt < NKT; kt++) {
        if (kt + 1 < NKT) cp_wait<1>(); else cp_wait<0>();
        __syncthreads();
        if (kt + 2 < NKT) {
            const uint32_t buf = smbase + ((kt + 2) % NSTAGE) * BUF_BYTES;
            #pragma unroll
            for (int i = 0; i < 4; i++) {
                cp_async16(buf + st_off[i],              Abase + (size_t)i * 32 * CC + (kt + 2) * GEMM_BK);
                cp_async16(buf + TILE_BYTES + st_off[i], Bbase + (size_t)i * 32 * CC + (kt + 2) * GEMM_BK);
            }
            cp_commit();
        }

        const uint32_t abuf = smbase + (kt % NSTAGE) * BUF_BYTES;
        const uint32_t bbuf = abuf + TILE_BYTES;

        #pragma unroll
        for (int kk = 0; kk < 4; kk++) {
            uint32_t af[4][4];
            #pragma unroll
            for (int mt = 0; mt < 4; mt++) {
                const int row = warp_m * 64 + mt * 16 + a_row_in;
                const uint32_t off = swz((uint32_t)row * 128 + (kk * 2 + a_chunk_hi) * 16);
                ldmatrix_x4(af[mt][0], af[mt][1], af[mt][2], af[mt][3], abuf + off);
                if (CVT_A) {
                    af[mt][0] = rnd_u(af[mt][0]); af[mt][1] = rnd_u(af[mt][1]);
                    af[mt][2] = rnd_u(af[mt][2]); af[mt][3] = rnd_u(af[mt][3]);
                }
            }
            uint32_t bf[4][2];
            #pragma unroll
            for (int pair = 0; pair < 2; pair++) {
                const int row = warp_n * 32 + pair * 16 + b_nt_off + b_row_in;
                const uint32_t off = swz((uint32_t)row * 128 + (kk * 2 + b_chunk_hi) * 16);
                uint32_t r0, r1, r2, r3;
                ldmatrix_x4(r0, r1, r2, r3, bbuf + off);
                if (CVT_B) {
                    r0 = rnd_u(r0); r1 = rnd_u(r1); r2 = rnd_u(r2); r3 = rnd_u(r3);
                }
                bf[pair * 2 + 0][0] = r0; bf[pair * 2 + 0][1] = r1;
                bf[pair * 2 + 1][0] = r2; bf[pair * 2 + 1][1] = r3;
            }
            #pragma unroll
            for (int mt = 0; mt < 4; mt++)
                #pragma unroll
                for (int nt = 0; nt < 4; nt++)
                    mma_tf32(acc[mt][nt][0], acc[mt][nt][1], acc[mt][nt][2], acc[mt][nt][3],
                             af[mt][0], af[mt][1], af[mt][2], af[mt][3],
                             bf[nt][0], bf[nt][1]);
        }
    }

    // epilogue
    const int er = warp_m * 64 + (lane >> 2);
    const int ec = warp_n * 32 + (lane & 3) * 2;
    #pragma unroll
    for (int mt = 0; mt < 4; mt++) {
        #pragma unroll
        for (int nt = 0; nt < 4; nt++) {
            const int row = bm + er + mt * 16;
            const int col = bn + ec + nt * 8;
            float2 lo = make_float2(acc[mt][nt][0], acc[mt][nt][1]);
            float2 hi = make_float2(acc[mt][nt][2], acc[mt][nt][3]);
            if (bias) {
                const float b0 = bias[col], b1 = bias[col + 1];
                lo.x += b0; lo.y += b1; hi.x += b0; hi.y += b1;
            }
            *(float2*)(C + (size_t)row * CC + col)       = lo;
            *(float2*)(C + (size_t)(row + 8) * CC + col) = hi;
        }
    }
}

// -------------------- flow-guided gather + aggregation (v5: packed LDS.64) ----
// Block = (hd, t, 16x16 h/w tile), 256 threads.
// s_pack[pl*9+k] = (attn_weight, v_row_offset_as_float_bits) -> stage 2 does
// ONE LDS.64 per k instead of two LDS.32. smem total 45 KB (same occupancy
// regime as the 176us best: ~4-5 CTAs/SM).
__global__ __launch_bounds__(256)
void gather_agg_kernel(const float* __restrict__ v,
                       const float* __restrict__ attn,
                       const int*   __restrict__ flows,
                       float* __restrict__ agg)
{
    __shared__ float2 s_pack[256 * KNBR];       // 18 KB: .x = attn, .y = voff bits
    __shared__ int    s_flows[256 * KNBR * 3];  // 27 KB

    int b = blockIdx.x;
    const int w0 = (b & 7) << 4; b >>= 3;
    const int h0 = (b & 7) << 4; b >>= 3;
    const int t  = b & 3;
    const int hd = b >> 2;

    const int tid = threadIdx.x;

    // ---- stage 0: coalesced staging (16 row-segments) ----
    const size_t pos00 = ((size_t)((hd * TT + t) * HH + h0)) * WW + w0;
    {
        const float* ab = attn + pos00 * KNBR;
        #pragma unroll
        for (int j = tid; j < 16 * 144; j += 256) {      // 9 iters
            const int r = j / 144;
            const int c = j - r * 144;
            s_pack[r * 144 + c].x = __ldg(ab + (size_t)r * (WW * KNBR) + c);
        }
        const int* fb = flows + pos00 * (KNBR * 3);
        #pragma unroll
        for (int j = tid; j < 16 * 432; j += 256) {      // 27 iters
            const int r = j / 432;
            const int c = j - r * 432;
            s_flows[r * 432 + c] = __ldg(fb + (size_t)r * (WW * KNBR * 3) + c);
        }
    }
    __syncthreads();

    // ---- stage 1: clipped v-row offsets into .y ----
    {
        const int pl = tid;
        const int w = w0 + (pl & 15);
        const int h = h0 + (pl >> 4);
        #pragma unroll
        for (int k = 0; k < KNBR; k++) {
            const int dt = s_flows[pl * 27 + k * 3 + 0];
            const int dh = s_flows[pl * 27 + k * 3 + 1];
            const int dw = s_flows[pl * 27 + k * 3 + 2];
            const int tt = min(max(t + dt, 0), TT - 1);
            const int hh = min(max(h + dh, 0), HH - 1);
            const int ww = min(max(w + dw, 0), WW - 1);
            s_pack[pl * KNBR + k].y = __int_as_float(((tt * HH + hh) * WW + ww) * CC);
        }
    }
    __syncthreads();

    // ---- stage 2: gather + weighted sum (one LDS.64 per k) ----
    const int fq  = tid & 7;
    const int pl0 = tid >> 3;                // 0..31; pl = pl0 + 32*i
    const int fbyte = hd * FF + fq * 4;
    const float* vb = v + fbyte;
    float* op = agg + ((size_t)((t * HH + (h0 + (pl0 >> 4))) * WW + (w0 + (pl0 & 15)))) * CC + fbyte;
    int sb = pl0 * KNBR;

    #pragma unroll
    for (int i = 0; i < 8; i++) {
        float4 acc = make_float4(0.f, 0.f, 0.f, 0.f);
        #pragma unroll
        for (int k = 0; k < KNBR; k++) {
            const float2 p = s_pack[sb + k];
            const float4 vv = *(const float4*)(vb + __float_as_int(p.y));
            acc.x += p.x * vv.x; acc.y += p.x * vv.y;
            acc.z += p.x * vv.z; acc.w += p.x * vv.w;
        }
        uint4 o;
        o.x = f2tf32(acc.x); o.y = f2tf32(acc.y);
        o.z = f2tf32(acc.z); o.w = f2tf32(acc.w);
        *(uint4*)op = o;
        sb += 32 * KNBR;                 // next 32 positions
        op += (size_t)2 * WW * CC;       // +2 h-rows
    }
}

// -------------------- launch --------------------
extern "C" void kernel_launch(void* const* d_in, const int* in_sizes, int n_in,
                              void* d_out, int out_size)
{
    const float* x      = (const float*)d_in[0];
    const float* attn   = (const float*)d_in[1];
    const int*   flows  = (const int*)  d_in[2];
    const float* v_w    = (const float*)d_in[3];
    const float* proj_w = (const float*)d_in[4];
    const float* proj_b = (const float*)d_in[5];
    float* out = (float*)d_out;

    float *v_buf, *agg_buf, *wv, *wp;
    cudaGetSymbolAddress((void**)&v_buf,   g_v);
    cudaGetSymbolAddress((void**)&agg_buf, g_agg);
    cudaGetSymbolAddress((void**)&wv,      g_wv);
    cudaGetSymbolAddress((void**)&wp,      g_wp);

    cudaFuncSetAttribute(gemm_tf32_mma_kernel<true, false>,
                         cudaFuncAttributeMaxDynamicSharedMemorySize, DSMEM_BYTES);
    cudaFuncSetAttribute(gemm_tf32_mma_kernel<false, false>,
                         cudaFuncAttributeMaxDynamicSharedMemorySize, DSMEM_BYTES);

    // 0) pre-round weights (tiny: 2 x 256KB)
    {
        const int n4w = CC * CC / 4;   // 16384
        cvt_tf32_kernel<<<n4w / 256, 256>>>(v_w, wv, n4w);
        cvt_tf32_kernel<<<n4w / 256, 256>>>(proj_w, wp, n4w);
    }

    dim3 ggrid(CC / GEMM_BN, MDIM / GEMM_BM);   // (2, 512)

    // 1) v = x @ v_w.T   (A rounded in-register — best measured variant; B pre-rounded)
    gemm_tf32_mma_kernel<true, false><<<ggrid, 256, DSMEM_BYTES>>>(x, wv, nullptr, v_buf);

    // 2) gather + weighted aggregation (packed LDS.64)
    {
        const int blocks = HDN * TT * 8 * 8;     // 2048
        gather_agg_kernel<<<blocks, 256>>>(v_buf, attn, flows, agg_buf);
    }

    // 3) out = agg @ proj_w.T + proj_b  (both operands pre-rounded)
    gemm_tf32_mma_kernel<false, false><<<ggrid, 256, DSMEM_BYTES>>>(agg_buf, wp, proj_b, out);
}